// round 2
// baseline (speedup 1.0000x reference)
#include <cuda_runtime.h>
#include <math.h>

#define DIMN 1024
#define BATCH 8
#define LSEQ 2048
#define M_TOK (BATCH*LSEQ)   /* 16384 tokens */
#define ACTC 256
#define HIDC 256
#define EPSV 1e-6f

// ---------------- scratch (device globals; no runtime allocation) ------------
__device__ float g_xn[(size_t)M_TOK*DIMN];   // rmsnorm output
__device__ float g_xc[(size_t)M_TOK*DIMN];   // conv out, later reused as y2 (post-gate)
__device__ float g_y [(size_t)M_TOK*DIMN];   // y = x_conv + x_rec
__device__ float g_t1[(size_t)M_TOK*DIMN];   // W1 pre-activation
__device__ float g_h [(size_t)M_TOK*HIDC];   // FFN hidden (post-gelu)

// ---------------- RMSNorm --------------------------------------------------
__global__ void rmsnorm_kernel(const float* __restrict__ x,
                               const float* __restrict__ w,
                               float* __restrict__ xn)
{
    int m = blockIdx.x;
    int t = threadIdx.x;                       // 256 threads, 4 floats each
    const float4* xr = (const float4*)(x + (size_t)m*DIMN);
    float4*       xo = (float4*)(xn + (size_t)m*DIMN);
    float4 v = xr[t];
    float ss = v.x*v.x + v.y*v.y + v.z*v.z + v.w*v.w;
    __shared__ float red[8];
    #pragma unroll
    for (int o = 16; o > 0; o >>= 1) ss += __shfl_xor_sync(0xffffffffu, ss, o);
    if ((t & 31) == 0) red[t >> 5] = ss;
    __syncthreads();
    if (t < 8) {
        float s = red[t];
        #pragma unroll
        for (int o = 4; o > 0; o >>= 1) s += __shfl_xor_sync(0xffu, s, o);
        if (t == 0) red[0] = s;
    }
    __syncthreads();
    float scale = rsqrtf(red[0] * (1.0f/DIMN) + EPSV);
    float4 wv = ((const float4*)w)[t];
    float4 o4;
    o4.x = v.x*scale*wv.x;  o4.y = v.y*scale*wv.y;
    o4.z = v.z*scale*wv.z;  o4.w = v.w*scale*wv.w;
    xo[t] = o4;
}

// ---------------- depthwise conv (K=5, pad=2, cross-correlation) ------------
__global__ void dwconv_kernel(const float* __restrict__ xn,
                              const float* __restrict__ dw_w,   // [DIM,1,5]
                              const float* __restrict__ dw_b,
                              float* __restrict__ xc)
{
    int idx = blockIdx.x * 256 + threadIdx.x;          // m*DIM + d
    int d = idx & (DIMN - 1);
    int m = idx >> 10;
    int l = m & (LSEQ - 1);
    float w0 = dw_w[d*5+0], w1 = dw_w[d*5+1], w2 = dw_w[d*5+2],
          w3 = dw_w[d*5+3], w4 = dw_w[d*5+4];
    float acc = dw_b[d];
    if (l >= 2)        acc += xn[idx - 2*DIMN] * w0;
    if (l >= 1)        acc += xn[idx - 1*DIMN] * w1;
    acc += xn[idx] * w2;
    if (l <= LSEQ - 2) acc += xn[idx + 1*DIMN] * w3;
    if (l <= LSEQ - 3) acc += xn[idx + 2*DIMN] * w4;
    xc[idx] = acc;
}

// ---------------- serial leaky-integrator scan (c < ACT) --------------------
__global__ void scan_kernel(const float* __restrict__ xn,
                            float* __restrict__ y,
                            const float* __restrict__ alpha,
                            const float* __restrict__ beta)
{
    int c = threadIdx.x;                 // 0..255
    int b = blockIdx.x;                  // 0..7
    float a = alpha[c], be = beta[c], h = 0.f;
    size_t base = (size_t)b * LSEQ * DIMN + c;
    for (int l = 0; l < LSEQ; l++) {
        h = a*h + be*xn[base];
        y[base] += h;
        base += DIMN;
    }
}

// ---------------- SGEMM: C = A[M,K] * B[N,K]^T (+ epilogue variants) --------
// EPI 0: y    = acc + bias[n] + (n>=ACT ? xn[m,n] : 0)
// EPI 1: t1   = acc + bias[n]
// EPI 2: y2   = y[m,n] + sigmoid(t1[m,n]) * tanh(acc + bias[n])
// EPI 3: h    = gelu_exact(acc + bias[n])
// EPI 4: out  = y2[m,n] + acc + bias[n] + x[m,n]
template<int EPI>
__global__ void __launch_bounds__(256, 2)
sgemm_kernel(int M, int N, int K,
             const float* __restrict__ A,
             const float* __restrict__ B,
             const float* __restrict__ bias,
             float* __restrict__ C,
             const float* __restrict__ aux1,
             const float* __restrict__ aux2)
{
    constexpr int BM = 128, BN = 128, BK = 16;
    __shared__ float As[BK][BM];
    __shared__ float Bs[BK][BN];
    const int bm = blockIdx.y * BM;
    const int bn = blockIdx.x * BN;
    const int tid = threadIdx.x;
    const int tr = tid >> 4;     // 0..15
    const int tc = tid & 15;     // 0..15

    float acc[8][8];
    #pragma unroll
    for (int i = 0; i < 8; i++)
        #pragma unroll
        for (int j = 0; j < 8; j++) acc[i][j] = 0.f;

    for (int k0 = 0; k0 < K; k0 += BK) {
        #pragma unroll
        for (int i = 0; i < 2; i++) {
            int f4  = tid + 256*i;        // 0..511
            int row = f4 >> 2;            // 0..127
            int c4  = (f4 & 3) * 4;       // 0,4,8,12
            float4 av = *(const float4*)(A + (size_t)(bm+row)*K + k0 + c4);
            As[c4+0][row] = av.x; As[c4+1][row] = av.y;
            As[c4+2][row] = av.z; As[c4+3][row] = av.w;
            float4 bv = *(const float4*)(B + (size_t)(bn+row)*K + k0 + c4);
            Bs[c4+0][row] = bv.x; Bs[c4+1][row] = bv.y;
            Bs[c4+2][row] = bv.z; Bs[c4+3][row] = bv.w;
        }
        __syncthreads();
        #pragma unroll
        for (int kk = 0; kk < BK; kk++) {
            float4 a0 = *(const float4*)&As[kk][tr*8];
            float4 a1 = *(const float4*)&As[kk][tr*8+4];
            float4 b0 = *(const float4*)&Bs[kk][tc*8];
            float4 b1 = *(const float4*)&Bs[kk][tc*8+4];
            float ra[8] = {a0.x,a0.y,a0.z,a0.w,a1.x,a1.y,a1.z,a1.w};
            float rb[8] = {b0.x,b0.y,b0.z,b0.w,b1.x,b1.y,b1.z,b1.w};
            #pragma unroll
            for (int i = 0; i < 8; i++)
                #pragma unroll
                for (int j = 0; j < 8; j++)
                    acc[i][j] += ra[i]*rb[j];
        }
        __syncthreads();
    }

    #pragma unroll
    for (int i = 0; i < 8; i++) {
        int gm = bm + tr*8 + i;
        #pragma unroll
        for (int j = 0; j < 8; j++) {
            int gn = bn + tc*8 + j;
            float v = acc[i][j] + bias[gn];
            size_t off = (size_t)gm * N + gn;
            if (EPI == 0) {
                if (gn >= ACTC) v += aux1[off];      // N==DIM, xn stride matches
                C[off] = v;
            } else if (EPI == 1) {
                C[off] = v;
            } else if (EPI == 2) {
                float t1v = aux1[off];
                float s = 1.f / (1.f + expf(-t1v));
                C[off] = aux2[off] + s * tanhf(v);
            } else if (EPI == 3) {
                C[off] = 0.5f * v * (1.f + erff(v * 0.70710678118654752f));
            } else {
                C[off] = aux1[off] + v + aux2[off];
            }
        }
    }
}

// ---------------- host launcher ---------------------------------------------
extern "C" void kernel_launch(void* const* d_in, const int* in_sizes, int n_in,
                              void* d_out, int out_size)
{
    const float* x      = (const float*)d_in[0];
    const float* norm_w = (const float*)d_in[1];
    const float* dw_w   = (const float*)d_in[2];
    const float* dw_b   = (const float*)d_in[3];
    const float* pw_w   = (const float*)d_in[4];
    const float* pw_b   = (const float*)d_in[5];
    const float* alpha  = (const float*)d_in[6];
    const float* beta   = (const float*)d_in[7];
    const float* W1_w   = (const float*)d_in[8];
    const float* W1_b   = (const float*)d_in[9];
    const float* W2_w   = (const float*)d_in[10];
    const float* W2_b   = (const float*)d_in[11];
    const float* down_w = (const float*)d_in[12];
    const float* down_b = (const float*)d_in[13];
    const float* up_w   = (const float*)d_in[14];
    const float* up_b   = (const float*)d_in[15];
    float* out = (float*)d_out;

    float *p_xn, *p_xc, *p_y, *p_t1, *p_h;
    cudaGetSymbolAddress((void**)&p_xn, g_xn);
    cudaGetSymbolAddress((void**)&p_xc, g_xc);
    cudaGetSymbolAddress((void**)&p_y,  g_y);
    cudaGetSymbolAddress((void**)&p_t1, g_t1);
    cudaGetSymbolAddress((void**)&p_h,  g_h);

    // 1) RMSNorm
    rmsnorm_kernel<<<M_TOK, 256>>>(x, norm_w, p_xn);
    // 2) depthwise conv
    dwconv_kernel<<<(M_TOK*DIMN)/256, 256>>>(p_xn, dw_w, dw_b, p_xc);
    // 3) pointwise GEMM: y = xc @ pw^T + pw_b  (+ xn for channels >= ACT)
    sgemm_kernel<0><<<dim3(DIMN/128, M_TOK/128), 256>>>(
        M_TOK, DIMN, DIMN, p_xc, pw_w, pw_b, p_y, p_xn, nullptr);
    // 4) recurrence: y[:, :, :ACT] += scan(xn[:, :, :ACT])
    scan_kernel<<<BATCH, ACTC>>>(p_xn, p_y, alpha, beta);
    // 5) t1 = y @ W1^T + b1
    sgemm_kernel<1><<<dim3(DIMN/128, M_TOK/128), 256>>>(
        M_TOK, DIMN, DIMN, p_y, W1_w, W1_b, p_t1, nullptr, nullptr);
    // 6) y2 = y + sigmoid(t1) * tanh(y @ W2^T + b2)   (y2 -> g_xc, no in-place race)
    sgemm_kernel<2><<<dim3(DIMN/128, M_TOK/128), 256>>>(
        M_TOK, DIMN, DIMN, p_y, W2_w, W2_b, p_xc, p_t1, p_y);
    // 7) h = gelu(y2 @ down^T + down_b)
    sgemm_kernel<3><<<dim3(HIDC/128, M_TOK/128), 256>>>(
        M_TOK, HIDC, DIMN, p_xc, down_w, down_b, p_h, nullptr, nullptr);
    // 8) out = y2 + h @ up^T + up_b + x   (residual)
    sgemm_kernel<4><<<dim3(DIMN/128, M_TOK/128), 256>>>(
        M_TOK, DIMN, HIDC, p_h, up_w, up_b, out, p_xc, x);
}

// round 4
// speedup vs baseline: 4.1040x; 4.1040x over previous
#include <cuda_runtime.h>
#include <cuda_bf16.h>
#include <math.h>
#include <stdint.h>

#define DIMN 1024
#define BATCH 8
#define LSEQ 2048
#define M_TOK (BATCH*LSEQ)
#define ACTC 256
#define HIDC 256
#define EPSV 1e-6f
#define NCHUNK 8
#define CHUNKL 256

// ---------------- scratch ---------------------------------------------------
__device__ float g_xn[(size_t)M_TOK*DIMN];
__device__ float g_xc[(size_t)M_TOK*DIMN];   // conv out, later y2
__device__ float g_y [(size_t)M_TOK*DIMN];
__device__ float g_t1[(size_t)M_TOK*DIMN];
__device__ float g_h [(size_t)M_TOK*HIDC];
__device__ __nv_bfloat16 g_ahi[(size_t)M_TOK*DIMN];
__device__ __nv_bfloat16 g_alo[(size_t)M_TOK*DIMN];
__device__ __nv_bfloat16 g_whi[(size_t)DIMN*DIMN];
__device__ __nv_bfloat16 g_wlo[(size_t)DIMN*DIMN];
__device__ float g_hend[BATCH*NCHUNK*ACTC];

// ---------------- helpers ---------------------------------------------------
__device__ __forceinline__ uint32_t smem_u32(const void* p) {
    uint32_t a;
    asm("{ .reg .u64 t; cvta.to.shared.u64 t, %1; cvt.u32.u64 %0, t; }" : "=r"(a) : "l"(p));
    return a;
}
__device__ __forceinline__ void cpasync16(uint32_t saddr, const void* g) {
    asm volatile("cp.async.cg.shared.global [%0], [%1], 16;" :: "r"(saddr), "l"(g) : "memory");
}
#define CP_COMMIT() asm volatile("cp.async.commit_group;" ::: "memory")

#define LDSM4(r, addr)                                                          \
    asm volatile("ldmatrix.sync.aligned.m8n8.x4.shared.b16 {%0,%1,%2,%3}, [%4];" \
        : "=r"((r)[0]), "=r"((r)[1]), "=r"((r)[2]), "=r"((r)[3]) : "r"(addr))

#define MMA16816(c, a, b0, b1)                                                  \
    asm volatile("mma.sync.aligned.m16n8k16.row.col.f32.bf16.bf16.f32 "         \
        "{%0,%1,%2,%3},{%4,%5,%6,%7},{%8,%9},{%0,%1,%2,%3};"                    \
        : "+f"((c)[0]), "+f"((c)[1]), "+f"((c)[2]), "+f"((c)[3])                \
        : "r"((a)[0]), "r"((a)[1]), "r"((a)[2]), "r"((a)[3]), "r"(b0), "r"(b1))

// smem: padded tiles 128 rows x 32 cols bf16, stride 40 elems (80B)
#define TPAD 40
#define TSE  (128*TPAD)           /* elems per tile  */
#define BUFE (4*TSE)              /* elems per buffer (Ahi,Alo,Bhi,Blo) */
#define SM_TOT (2*BUFE*2)         /* bytes: 81920 */

// ---------------- split-bf16 HMMA GEMM: C = A[M,K] * B[N,K]^T ---------------
// EPI 0: y   = acc + bias + (gn>=ACT ? aux1 : 0)
// EPI 1: t1  = acc + bias
// EPI 2: y2  = aux2 + sigmoid(aux1) * tanh(acc + bias)
// EPI 3: h   = gelu_exact(acc + bias)
// EPI 4: out = aux1 + acc + bias + aux2
template<int EPI>
__global__ void __launch_bounds__(256)
tgemm(int M, int N, int K,
      const __nv_bfloat16* __restrict__ Ahi, const __nv_bfloat16* __restrict__ Alo,
      const __nv_bfloat16* __restrict__ Bhi, const __nv_bfloat16* __restrict__ Blo,
      const float* __restrict__ bias, float* __restrict__ C,
      const float* __restrict__ aux1, const float* __restrict__ aux2)
{
    extern __shared__ __nv_bfloat16 sm[];
    const uint32_t sb = smem_u32(sm);
    const int t = threadIdx.x;
    const int bm = blockIdx.y * 128;
    const int bn = blockIdx.x * 128;

    const int wid = t >> 5, l = t & 31;
    const int wm = wid & 1;          // 0..1 : 64 rows each
    const int wn = wid >> 1;         // 0..3 : 32 cols each

    float c[4][4][4];
    #pragma unroll
    for (int i = 0; i < 4; i++)
        #pragma unroll
        for (int j = 0; j < 4; j++)
            #pragma unroll
            for (int k = 0; k < 4; k++) c[i][j][k] = 0.f;

    auto load_buf = [&](int buf, int k0) {
        uint32_t dbase = sb + (uint32_t)buf * BUFE * 2;
        #pragma unroll
        for (int i = 0; i < 2; i++) {
            int q = t + 256*i;                 // 0..511
            int row = q >> 2;
            int col = (q & 3) * 8;             // elems
            uint32_t doff = (uint32_t)(row*TPAD + col) * 2;
            size_t ga = (size_t)(bm + row) * K + k0 + col;
            size_t gb = (size_t)(bn + row) * K + k0 + col;
            cpasync16(dbase + 0*TSE*2 + doff, Ahi + ga);
            cpasync16(dbase + 1*TSE*2 + doff, Alo + ga);
            cpasync16(dbase + 2*TSE*2 + doff, Bhi + gb);
            cpasync16(dbase + 3*TSE*2 + doff, Blo + gb);
        }
        CP_COMMIT();
    };

    const int KB = K >> 5;
    load_buf(0, 0);

    const int arow = wm*64 + (l & 15);
    const uint32_t acol = (uint32_t)((l >> 4) << 3);
    const int brow = wn*32 + (l & 7) + ((l & 16) >> 1);
    const uint32_t bcol = (uint32_t)(l & 8);

    for (int kb = 0; kb < KB; kb++) {
        if (kb + 1 < KB) {
            load_buf((kb+1) & 1, (kb+1)*32);
            asm volatile("cp.async.wait_group 1;" ::: "memory");
        } else {
            asm volatile("cp.async.wait_group 0;" ::: "memory");
        }
        __syncthreads();

        uint32_t base = sb + (uint32_t)(kb & 1) * BUFE * 2;
        #pragma unroll
        for (int ks = 0; ks < 2; ks++) {
            uint32_t ahi[4][4], alo[4][4], bhi[2][4], blo[2][4];
            #pragma unroll
            for (int mt = 0; mt < 4; mt++) {
                uint32_t off = (uint32_t)((arow + mt*16)*TPAD + acol + ks*16) * 2;
                LDSM4(ahi[mt], base + 0*TSE*2 + off);
                LDSM4(alo[mt], base + 1*TSE*2 + off);
            }
            #pragma unroll
            for (int j = 0; j < 2; j++) {
                uint32_t off = (uint32_t)((brow + j*16)*TPAD + bcol + ks*16) * 2;
                LDSM4(bhi[j], base + 2*TSE*2 + off);
                LDSM4(blo[j], base + 3*TSE*2 + off);
            }
            #pragma unroll
            for (int mt = 0; mt < 4; mt++)
                #pragma unroll
                for (int nt = 0; nt < 4; nt++) {
                    int j = nt >> 1, h = (nt & 1) * 2;
                    MMA16816(c[mt][nt], ahi[mt], bhi[j][h], bhi[j][h+1]);
                    MMA16816(c[mt][nt], ahi[mt], blo[j][h], blo[j][h+1]);
                    MMA16816(c[mt][nt], alo[mt], bhi[j][h], bhi[j][h+1]);
                }
        }
        __syncthreads();
    }

    // ---- epilogue ----
    const int gid = l >> 2, tig = l & 3;
    #pragma unroll
    for (int mt = 0; mt < 4; mt++) {
        #pragma unroll
        for (int half = 0; half < 2; half++) {
            int gm = bm + wm*64 + mt*16 + gid + half*8;
            size_t rowoff = (size_t)gm * N;
            #pragma unroll
            for (int nt = 0; nt < 4; nt++) {
                int gn = bn + wn*32 + nt*8 + tig*2;
                float v0 = c[mt][nt][half*2+0] + bias[gn];
                float v1 = c[mt][nt][half*2+1] + bias[gn+1];
                float2 o;
                if (EPI == 0) {
                    if (gn >= ACTC) {
                        float2 a = *(const float2*)(aux1 + rowoff + gn);
                        v0 += a.x; v1 += a.y;
                    }
                    o.x = v0; o.y = v1;
                } else if (EPI == 1) {
                    o.x = v0; o.y = v1;
                } else if (EPI == 2) {
                    float2 a = *(const float2*)(aux1 + rowoff + gn);
                    float2 b = *(const float2*)(aux2 + rowoff + gn);
                    o.x = b.x + tanhf(v0) / (1.f + expf(-a.x));
                    o.y = b.y + tanhf(v1) / (1.f + expf(-a.y));
                } else if (EPI == 3) {
                    o.x = 0.5f*v0*(1.f + erff(v0*0.70710678118654752f));
                    o.y = 0.5f*v1*(1.f + erff(v1*0.70710678118654752f));
                } else {
                    float2 a = *(const float2*)(aux1 + rowoff + gn);
                    float2 b = *(const float2*)(aux2 + rowoff + gn);
                    o.x = a.x + v0 + b.x;
                    o.y = a.y + v1 + b.y;
                }
                *(float2*)(C + rowoff + gn) = o;
            }
        }
    }
}

// ---------------- fp32 -> bf16 hi/lo split ----------------------------------
__global__ void split_kernel(const float* __restrict__ s,
                             __nv_bfloat16* __restrict__ hi,
                             __nv_bfloat16* __restrict__ lo)
{
    int i = blockIdx.x * 256 + threadIdx.x;
    float4 v = ((const float4*)s)[i];
    __nv_bfloat16 hx = __float2bfloat16(v.x), hy = __float2bfloat16(v.y);
    __nv_bfloat16 hz = __float2bfloat16(v.z), hw = __float2bfloat16(v.w);
    __nv_bfloat16 lx = __float2bfloat16(v.x - __bfloat162float(hx));
    __nv_bfloat16 ly = __float2bfloat16(v.y - __bfloat162float(hy));
    __nv_bfloat16 lz = __float2bfloat16(v.z - __bfloat162float(hz));
    __nv_bfloat16 lw = __float2bfloat16(v.w - __bfloat162float(hw));
    ((__nv_bfloat162*)hi)[2*i]   = __nv_bfloat162(hx, hy);
    ((__nv_bfloat162*)hi)[2*i+1] = __nv_bfloat162(hz, hw);
    ((__nv_bfloat162*)lo)[2*i]   = __nv_bfloat162(lx, ly);
    ((__nv_bfloat162*)lo)[2*i+1] = __nv_bfloat162(lz, lw);
}

// ---------------- RMSNorm ---------------------------------------------------
__global__ void rmsnorm_kernel(const float* __restrict__ x,
                               const float* __restrict__ w,
                               float* __restrict__ xn)
{
    int m = blockIdx.x;
    int t = threadIdx.x;
    const float4* xr = (const float4*)(x + (size_t)m*DIMN);
    float4*       xo = (float4*)(xn + (size_t)m*DIMN);
    float4 v = xr[t];
    float ss = v.x*v.x + v.y*v.y + v.z*v.z + v.w*v.w;
    __shared__ float red[8];
    #pragma unroll
    for (int o = 16; o > 0; o >>= 1) ss += __shfl_xor_sync(0xffffffffu, ss, o);
    if ((t & 31) == 0) red[t >> 5] = ss;
    __syncthreads();
    if (t < 8) {
        float s = red[t];
        #pragma unroll
        for (int o = 4; o > 0; o >>= 1) s += __shfl_xor_sync(0xffu, s, o);
        if (t == 0) red[0] = s;
    }
    __syncthreads();
    float scale = rsqrtf(red[0] * (1.0f/DIMN) + EPSV);
    float4 wv = ((const float4*)w)[t];
    float4 o4;
    o4.x = v.x*scale*wv.x;  o4.y = v.y*scale*wv.y;
    o4.z = v.z*scale*wv.z;  o4.w = v.w*scale*wv.w;
    xo[t] = o4;
}

// ---------------- depthwise conv -------------------------------------------
__global__ void dwconv_kernel(const float* __restrict__ xn,
                              const float* __restrict__ dw_w,
                              const float* __restrict__ dw_b,
                              float* __restrict__ xc)
{
    int idx = blockIdx.x * 256 + threadIdx.x;
    int d = idx & (DIMN - 1);
    int m = idx >> 10;
    int l = m & (LSEQ - 1);
    float w0 = dw_w[d*5+0], w1 = dw_w[d*5+1], w2 = dw_w[d*5+2],
          w3 = dw_w[d*5+3], w4 = dw_w[d*5+4];
    float acc = dw_b[d];
    if (l >= 2)        acc += xn[idx - 2*DIMN] * w0;
    if (l >= 1)        acc += xn[idx - 1*DIMN] * w1;
    acc += xn[idx] * w2;
    if (l <= LSEQ - 2) acc += xn[idx + 1*DIMN] * w3;
    if (l <= LSEQ - 3) acc += xn[idx + 2*DIMN] * w4;
    xc[idx] = acc;
}

// ---------------- chunked scan ----------------------------------------------
__global__ void scan_p1(const float* __restrict__ xn,
                        const float* __restrict__ alpha,
                        const float* __restrict__ beta,
                        float* __restrict__ hend)
{
    int c = threadIdx.x, ch = blockIdx.x, b = blockIdx.y;
    float a = alpha[c], be = beta[c], h = 0.f;
    size_t base = ((size_t)b*LSEQ + ch*CHUNKL)*DIMN + c;
    for (int i = 0; i < CHUNKL; i++) { h = fmaf(a, h, be*xn[base]); base += DIMN; }
    hend[(b*NCHUNK + ch)*ACTC + c] = h;
}

__global__ void scan_p2(const float* __restrict__ xn,
                        float* __restrict__ y,
                        const float* __restrict__ alpha,
                        const float* __restrict__ beta,
                        const float* __restrict__ hend)
{
    int c = threadIdx.x, ch = blockIdx.x, b = blockIdx.y;
    float a = alpha[c], be = beta[c];
    float ap = a;
    #pragma unroll
    for (int i = 0; i < 8; i++) ap = ap*ap;       // a^256
    float h = 0.f;
    for (int j = 0; j < ch; j++) h = ap*h + hend[(b*NCHUNK + j)*ACTC + c];
    size_t base = ((size_t)b*LSEQ + ch*CHUNKL)*DIMN + c;
    for (int i = 0; i < CHUNKL; i++) {
        h = fmaf(a, h, be*xn[base]);
        y[base] += h;
        base += DIMN;
    }
}

// ---------------- host launcher ---------------------------------------------
extern "C" void kernel_launch(void* const* d_in, const int* in_sizes, int n_in,
                              void* d_out, int out_size)
{
    const float* x      = (const float*)d_in[0];
    const float* norm_w = (const float*)d_in[1];
    const float* dw_w   = (const float*)d_in[2];
    const float* dw_b   = (const float*)d_in[3];
    const float* pw_w   = (const float*)d_in[4];
    const float* pw_b   = (const float*)d_in[5];
    const float* alpha  = (const float*)d_in[6];
    const float* beta   = (const float*)d_in[7];
    const float* W1_w   = (const float*)d_in[8];
    const float* W1_b   = (const float*)d_in[9];
    const float* W2_w   = (const float*)d_in[10];
    const float* W2_b   = (const float*)d_in[11];
    const float* down_w = (const float*)d_in[12];
    const float* down_b = (const float*)d_in[13];
    const float* up_w   = (const float*)d_in[14];
    const float* up_b   = (const float*)d_in[15];
    float* out = (float*)d_out;

    float *p_xn, *p_xc, *p_y, *p_t1, *p_h, *p_hend;
    __nv_bfloat16 *p_ahi, *p_alo, *p_whi, *p_wlo;
    cudaGetSymbolAddress((void**)&p_xn, g_xn);
    cudaGetSymbolAddress((void**)&p_xc, g_xc);
    cudaGetSymbolAddress((void**)&p_y,  g_y);
    cudaGetSymbolAddress((void**)&p_t1, g_t1);
    cudaGetSymbolAddress((void**)&p_h,  g_h);
    cudaGetSymbolAddress((void**)&p_hend, g_hend);
    cudaGetSymbolAddress((void**)&p_ahi, g_ahi);
    cudaGetSymbolAddress((void**)&p_alo, g_alo);
    cudaGetSymbolAddress((void**)&p_whi, g_whi);
    cudaGetSymbolAddress((void**)&p_wlo, g_wlo);

    cudaFuncSetAttribute(tgemm<0>, cudaFuncAttributeMaxDynamicSharedMemorySize, SM_TOT);
    cudaFuncSetAttribute(tgemm<1>, cudaFuncAttributeMaxDynamicSharedMemorySize, SM_TOT);
    cudaFuncSetAttribute(tgemm<2>, cudaFuncAttributeMaxDynamicSharedMemorySize, SM_TOT);
    cudaFuncSetAttribute(tgemm<3>, cudaFuncAttributeMaxDynamicSharedMemorySize, SM_TOT);
    cudaFuncSetAttribute(tgemm<4>, cudaFuncAttributeMaxDynamicSharedMemorySize, SM_TOT);

    const dim3 gBig(DIMN/128, M_TOK/128);     // (8, 128)
    const dim3 gDown(HIDC/128, M_TOK/128);    // (2, 128)

    // 1) norm + conv
    rmsnorm_kernel<<<M_TOK, 256>>>(x, norm_w, p_xn);
    dwconv_kernel<<<(M_TOK*DIMN)/256, 256>>>(p_xn, dw_w, dw_b, p_xc);
    // 2) pointwise GEMM: y = xc @ pw^T + pw_b (+ xn for n>=ACT)
    split_kernel<<<(M_TOK*DIMN)/1024, 256>>>(p_xc, p_ahi, p_alo);
    split_kernel<<<(DIMN*DIMN)/1024, 256>>>(pw_w, p_whi, p_wlo);
    tgemm<0><<<gBig, 256, SM_TOT>>>(M_TOK, DIMN, DIMN, p_ahi, p_alo, p_whi, p_wlo,
                                    pw_b, p_y, p_xn, nullptr);
    // 3) recurrence adds into y[:, :ACT]
    scan_p1<<<dim3(NCHUNK, BATCH), ACTC>>>(p_xn, alpha, beta, p_hend);
    scan_p2<<<dim3(NCHUNK, BATCH), ACTC>>>(p_xn, p_y, alpha, beta, p_hend);
    // 4) t1 = y @ W1^T + b1
    split_kernel<<<(M_TOK*DIMN)/1024, 256>>>(p_y, p_ahi, p_alo);
    split_kernel<<<(DIMN*DIMN)/1024, 256>>>(W1_w, p_whi, p_wlo);
    tgemm<1><<<gBig, 256, SM_TOT>>>(M_TOK, DIMN, DIMN, p_ahi, p_alo, p_whi, p_wlo,
                                    W1_b, p_t1, nullptr, nullptr);
    // 5) y2 = y + sigmoid(t1)*tanh(y @ W2^T + b2)  (A tiles unchanged = y)
    split_kernel<<<(DIMN*DIMN)/1024, 256>>>(W2_w, p_whi, p_wlo);
    tgemm<2><<<gBig, 256, SM_TOT>>>(M_TOK, DIMN, DIMN, p_ahi, p_alo, p_whi, p_wlo,
                                    W2_b, p_xc, p_t1, p_y);
    // 6) h = gelu(y2 @ down^T + down_b)
    split_kernel<<<(M_TOK*DIMN)/1024, 256>>>(p_xc, p_ahi, p_alo);
    split_kernel<<<(HIDC*DIMN)/1024, 256>>>(down_w, p_whi, p_wlo);
    tgemm<3><<<gDown, 256, SM_TOT>>>(M_TOK, HIDC, DIMN, p_ahi, p_alo, p_whi, p_wlo,
                                     down_b, p_h, nullptr, nullptr);
    // 7) out = y2 + h @ up^T + up_b + x
    split_kernel<<<(M_TOK*HIDC)/1024, 256>>>(p_h, p_ahi, p_alo);
    split_kernel<<<(DIMN*HIDC)/1024, 256>>>(up_w, p_whi, p_wlo);
    tgemm<4><<<gBig, 256, SM_TOT>>>(M_TOK, DIMN, HIDC, p_ahi, p_alo, p_whi, p_wlo,
                                    up_b, out, p_xc, x);
}

// round 9
// speedup vs baseline: 4.1483x; 1.0108x over previous
#include <cuda_runtime.h>
#include <cuda_fp16.h>
#include <math.h>
#include <stdint.h>

#define DIMN 1024
#define BATCH 8
#define LSEQ 2048
#define M_TOK (BATCH*LSEQ)
#define ACTC 256
#define HIDC 256
#define EPSV 1e-6f
#define NCHUNK 8
#define CHUNKL 256

// ---------------- scratch ---------------------------------------------------
__device__ float g_xn[(size_t)M_TOK*DIMN];
__device__ float g_xc[(size_t)M_TOK*DIMN];    // y2 fp32
__device__ float g_y [(size_t)M_TOK*DIMN];
__device__ float g_t1[(size_t)M_TOK*DIMN];
__device__ __half g_ahi [(size_t)M_TOK*DIMN];
__device__ __half g_alo [(size_t)M_TOK*DIMN];
__device__ __half g_a2hi[(size_t)M_TOK*DIMN];
__device__ __half g_a2lo[(size_t)M_TOK*DIMN];
__device__ __half g_bh  [(size_t)DIMN*DIMN];  // current weight, fp16 hi
__device__ float g_hend[BATCH*NCHUNK*ACTC];

// ---------------- helpers ---------------------------------------------------
__device__ __forceinline__ uint32_t smem_u32(const void* p) {
    uint32_t a;
    asm("{ .reg .u64 t; cvta.to.shared.u64 t, %1; cvt.u32.u64 %0, t; }" : "=r"(a) : "l"(p));
    return a;
}
__device__ __forceinline__ void cpasync16(uint32_t saddr, const void* g) {
    asm volatile("cp.async.cg.shared.global [%0], [%1], 16;" :: "r"(saddr), "l"(g) : "memory");
}
#define CP_COMMIT() asm volatile("cp.async.commit_group;" ::: "memory")

#define LDSM4(r, addr)                                                          \
    asm volatile("ldmatrix.sync.aligned.m8n8.x4.shared.b16 {%0,%1,%2,%3}, [%4];" \
        : "=r"((r)[0]), "=r"((r)[1]), "=r"((r)[2]), "=r"((r)[3]) : "r"(addr))

#define MMAH(c, a, b0, b1)                                                      \
    asm volatile("mma.sync.aligned.m16n8k16.row.col.f32.f16.f16.f32 "           \
        "{%0,%1,%2,%3},{%4,%5,%6,%7},{%8,%9},{%0,%1,%2,%3};"                    \
        : "+f"((c)[0]), "+f"((c)[1]), "+f"((c)[2]), "+f"((c)[3])                \
        : "r"((a)[0]), "r"((a)[1]), "r"((a)[2]), "r"((a)[3]), "r"(b0), "r"(b1))

// smem: rows of 32 fp16 padded to stride 40 halfs (80B) -> conflict-free LDSM
#define TPADH 40
#define AHI_B 0
#define ALO_B 10240
#define BH_B  20480
#define STAGE_B 40960
#define NSTAGE 3
#define SM_TOT (NSTAGE*STAGE_B)   /* 122880 */

// ---------------- split-fp16 2-pass HMMA GEMM: C = A[M,K]*B[N,K]^T ----------
// EPI 0: y   = acc + bias + (gn>=ACT ? aux1 : 0)
// EPI 1: t1  = acc + bias
// EPI 2: y2  = aux2 + sigmoid(aux1) * tanh(acc + bias)
// EPI 3: h   = gelu_exact(acc + bias)
// EPI 4: out = aux1 + acc + bias + aux2
template<int EPI, bool WF32, bool WSPLIT>
__global__ void __launch_bounds__(256)
tgemm(int M, int N, int K,
      const __half* __restrict__ Ahi, const __half* __restrict__ Alo,
      const __half* __restrict__ Bh,
      const float* __restrict__ bias, float* __restrict__ C,
      __half* __restrict__ Chi, __half* __restrict__ Clo,
      const float* __restrict__ aux1, const float* __restrict__ aux2)
{
    extern __shared__ char sm[];
    const uint32_t sb = smem_u32(sm);
    const int t = threadIdx.x;
    const int bm = blockIdx.y * 128;
    const int bn = blockIdx.x * 256;

    const int wid = t >> 5, l = t & 31;
    const int wm = wid & 1;           // 2 x 64 rows
    const int wn = wid >> 1;          // 4 x 64 cols

    float c[4][8][4];
    #pragma unroll
    for (int i = 0; i < 4; i++)
        #pragma unroll
        for (int j = 0; j < 8; j++)
            #pragma unroll
            for (int k = 0; k < 4; k++) c[i][j][k] = 0.f;

    auto load_buf = [&](int buf, int k0) {
        uint32_t dbase = sb + (uint32_t)buf * STAGE_B;
        #pragma unroll
        for (int i = 0; i < 8; i++) {
            int cid = t + 256*i;                  // 0..2047
            if (cid < 1024) {                     // A hi/lo: 512 chunks each
                int row = (cid & 511) >> 2;
                int cc  = cid & 3;
                uint32_t doff = (uint32_t)(row*80 + cc*16);
                const __half* src = (cid < 512) ? Ahi : Alo;
                uint32_t db = (cid < 512) ? AHI_B : ALO_B;
                cpasync16(dbase + db + doff, src + (size_t)(bm+row)*K + k0 + cc*8);
            } else {                              // B hi: 1024 chunks
                int q = cid - 1024;
                int row = q >> 2;
                int cc  = q & 3;
                cpasync16(dbase + BH_B + (uint32_t)(row*80 + cc*16),
                          Bh + (size_t)(bn+row)*K + k0 + cc*8);
            }
        }
        CP_COMMIT();
    };

    const int KB = K >> 5;
    load_buf(0, 0);
    if (KB > 1) load_buf(1, 32); else CP_COMMIT();

    const uint32_t acol = (uint32_t)((l >> 4) << 3);
    const int arow0 = wm*64 + (l & 15);
    const int brow0 = wn*64 + (l & 7) + ((l & 16) >> 1);
    const uint32_t bcol = (uint32_t)(l & 8);

    for (int kb = 0; kb < KB; kb++) {
        if (kb + 2 < KB) load_buf((kb+2) % NSTAGE, (kb+2)*32); else CP_COMMIT();
        asm volatile("cp.async.wait_group 2;" ::: "memory");
        __syncthreads();

        uint32_t base = sb + (uint32_t)(kb % NSTAGE) * STAGE_B;
        #pragma unroll
        for (int ks = 0; ks < 2; ks++) {
            uint32_t ahi[4][4], alo[4][4];
            #pragma unroll
            for (int mt = 0; mt < 4; mt++) {
                uint32_t off = (uint32_t)((arow0 + mt*16)*TPADH + acol + ks*16) * 2;
                LDSM4(ahi[mt], base + AHI_B + off);
                LDSM4(alo[mt], base + ALO_B + off);
            }
            #pragma unroll
            for (int j = 0; j < 4; j++) {
                uint32_t b[4];
                uint32_t off = (uint32_t)((brow0 + j*16)*TPADH + bcol + ks*16) * 2;
                LDSM4(b, base + BH_B + off);
                #pragma unroll
                for (int mt = 0; mt < 4; mt++) {
                    MMAH(c[mt][j*2+0], ahi[mt], b[0], b[1]);
                    MMAH(c[mt][j*2+0], alo[mt], b[0], b[1]);
                    MMAH(c[mt][j*2+1], ahi[mt], b[2], b[3]);
                    MMAH(c[mt][j*2+1], alo[mt], b[2], b[3]);
                }
            }
        }
        __syncthreads();
    }

    // ---- epilogue ----
    const int gid = l >> 2, tig = l & 3;
    #pragma unroll
    for (int mt = 0; mt < 4; mt++) {
        #pragma unroll
        for (int half = 0; half < 2; half++) {
            int gm = bm + wm*64 + mt*16 + gid + half*8;
            size_t rowoff = (size_t)gm * N;
            #pragma unroll
            for (int nt = 0; nt < 8; nt++) {
                int gn = bn + wn*64 + nt*8 + tig*2;
                float v0 = c[mt][nt][half*2+0] + bias[gn];
                float v1 = c[mt][nt][half*2+1] + bias[gn+1];
                float2 o;
                if (EPI == 0) {
                    if (gn >= ACTC) {
                        float2 a = *(const float2*)(aux1 + rowoff + gn);
                        v0 += a.x; v1 += a.y;
                    }
                    o.x = v0; o.y = v1;
                } else if (EPI == 1) {
                    o.x = v0; o.y = v1;
                } else if (EPI == 2) {
                    float2 a = *(const float2*)(aux1 + rowoff + gn);
                    float2 b = *(const float2*)(aux2 + rowoff + gn);
                    o.x = b.x + tanhf(v0) / (1.f + expf(-a.x));
                    o.y = b.y + tanhf(v1) / (1.f + expf(-a.y));
                } else if (EPI == 3) {
                    o.x = 0.5f*v0*(1.f + erff(v0*0.70710678118654752f));
                    o.y = 0.5f*v1*(1.f + erff(v1*0.70710678118654752f));
                } else {
                    float2 a = *(const float2*)(aux1 + rowoff + gn);
                    float2 b = *(const float2*)(aux2 + rowoff + gn);
                    o.x = a.x + v0 + b.x;
                    o.y = a.y + v1 + b.y;
                }
                if (WF32) *(float2*)(C + rowoff + gn) = o;
                if (WSPLIT) {
                    __half h0 = __float2half(o.x), h1 = __float2half(o.y);
                    __half l0 = __float2half(o.x - __half2float(h0));
                    __half l1 = __float2half(o.y - __half2float(h1));
                    *(__half2*)(Chi + rowoff + gn) = __half2(h0, h1);
                    *(__half2*)(Clo + rowoff + gn) = __half2(l0, l1);
                }
            }
        }
    }
}

// ---------------- fp32 -> fp16 (weights, hi only) ---------------------------
__global__ void whalf_kernel(const float* __restrict__ s, __half* __restrict__ h)
{
    int i = blockIdx.x * 256 + threadIdx.x;
    float4 v = ((const float4*)s)[i];
    ((__half2*)h)[2*i]   = __half2(__float2half(v.x), __float2half(v.y));
    ((__half2*)h)[2*i+1] = __half2(__float2half(v.z), __float2half(v.w));
}

// ---------------- RMSNorm ---------------------------------------------------
__global__ void rmsnorm_kernel(const float* __restrict__ x,
                               const float* __restrict__ w,
                               float* __restrict__ xn)
{
    int m = blockIdx.x;
    int t = threadIdx.x;
    const float4* xr = (const float4*)(x + (size_t)m*DIMN);
    float4*       xo = (float4*)(xn + (size_t)m*DIMN);
    float4 v = xr[t];
    float ss = v.x*v.x + v.y*v.y + v.z*v.z + v.w*v.w;
    __shared__ float red[8];
    #pragma unroll
    for (int o = 16; o > 0; o >>= 1) ss += __shfl_xor_sync(0xffffffffu, ss, o);
    if ((t & 31) == 0) red[t >> 5] = ss;
    __syncthreads();
    if (t < 8) {
        float s = red[t];
        #pragma unroll
        for (int o = 4; o > 0; o >>= 1) s += __shfl_xor_sync(0xffu, s, o);
        if (t == 0) red[0] = s;
    }
    __syncthreads();
    float scale = rsqrtf(red[0] * (1.0f/DIMN) + EPSV);
    float4 wv = ((const float4*)w)[t];
    float4 o4;
    o4.x = v.x*scale*wv.x;  o4.y = v.y*scale*wv.y;
    o4.z = v.z*scale*wv.z;  o4.w = v.w*scale*wv.w;
    xo[t] = o4;
}

// ---------------- depthwise conv + fused fp16 split -------------------------
__global__ void dwconv_split_kernel(const float* __restrict__ xn,
                                    const float* __restrict__ dw_w,
                                    const float* __restrict__ dw_b,
                                    __half* __restrict__ hi,
                                    __half* __restrict__ lo)
{
    int idx = blockIdx.x * 256 + threadIdx.x;
    int d = idx & (DIMN - 1);
    int m = idx >> 10;
    int l = m & (LSEQ - 1);
    float w0 = dw_w[d*5+0], w1 = dw_w[d*5+1], w2 = dw_w[d*5+2],
          w3 = dw_w[d*5+3], w4 = dw_w[d*5+4];
    float acc = dw_b[d];
    if (l >= 2)        acc += xn[idx - 2*DIMN] * w0;
    if (l >= 1)        acc += xn[idx - 1*DIMN] * w1;
    acc += xn[idx] * w2;
    if (l <= LSEQ - 2) acc += xn[idx + 1*DIMN] * w3;
    if (l <= LSEQ - 3) acc += xn[idx + 2*DIMN] * w4;
    __half h = __float2half(acc);
    hi[idx] = h;
    lo[idx] = __float2half(acc - __half2float(h));
}

// ---------------- chunked scan ----------------------------------------------
__global__ void scan_p1(const float* __restrict__ xn,
                        const float* __restrict__ alpha,
                        const float* __restrict__ beta,
                        float* __restrict__ hend)
{
    int c = threadIdx.x, ch = blockIdx.x, b = blockIdx.y;
    float a = alpha[c], be = beta[c], h = 0.f;
    size_t base = ((size_t)b*LSEQ + ch*CHUNKL)*DIMN + c;
    for (int i = 0; i < CHUNKL; i++) { h = fmaf(a, h, be*xn[base]); base += DIMN; }
    hend[(b*NCHUNK + ch)*ACTC + c] = h;
}

__global__ void scan_p2(const float* __restrict__ xn,
                        float* __restrict__ y,
                        const float* __restrict__ alpha,
                        const float* __restrict__ beta,
                        const float* __restrict__ hend,
                        __half* __restrict__ yhi,
                        __half* __restrict__ ylo)
{
    int c = threadIdx.x, ch = blockIdx.x, b = blockIdx.y;
    float a = alpha[c], be = beta[c];
    float ap = a;
    #pragma unroll
    for (int i = 0; i < 8; i++) ap = ap*ap;       // a^256
    float h = 0.f;
    for (int j = 0; j < ch; j++) h = ap*h + hend[(b*NCHUNK + j)*ACTC + c];
    size_t base = ((size_t)b*LSEQ + ch*CHUNKL)*DIMN + c;
    for (int i = 0; i < CHUNKL; i++) {
        h = fmaf(a, h, be*xn[base]);
        float yn = y[base] + h;
        y[base] = yn;
        __half hv = __float2half(yn);
        yhi[base] = hv;
        ylo[base] = __float2half(yn - __half2float(hv));
        base += DIMN;
    }
}

// ---------------- host launcher ---------------------------------------------
extern "C" void kernel_launch(void* const* d_in, const int* in_sizes, int n_in,
                              void* d_out, int out_size)
{
    const float* x      = (const float*)d_in[0];
    const float* norm_w = (const float*)d_in[1];
    const float* dw_w   = (const float*)d_in[2];
    const float* dw_b   = (const float*)d_in[3];
    const float* pw_w   = (const float*)d_in[4];
    const float* pw_b   = (const float*)d_in[5];
    const float* alpha  = (const float*)d_in[6];
    const float* beta   = (const float*)d_in[7];
    const float* W1_w   = (const float*)d_in[8];
    const float* W1_b   = (const float*)d_in[9];
    const float* W2_w   = (const float*)d_in[10];
    const float* W2_b   = (const float*)d_in[11];
    const float* down_w = (const float*)d_in[12];
    const float* down_b = (const float*)d_in[13];
    const float* up_w   = (const float*)d_in[14];
    const float* up_b   = (const float*)d_in[15];
    float* out = (float*)d_out;

    float *p_xn, *p_xc, *p_y, *p_t1, *p_hend;
    __half *p_ahi, *p_alo, *p_a2hi, *p_a2lo, *p_bh;
    cudaGetSymbolAddress((void**)&p_xn, g_xn);
    cudaGetSymbolAddress((void**)&p_xc, g_xc);
    cudaGetSymbolAddress((void**)&p_y,  g_y);
    cudaGetSymbolAddress((void**)&p_t1, g_t1);
    cudaGetSymbolAddress((void**)&p_hend, g_hend);
    cudaGetSymbolAddress((void**)&p_ahi,  g_ahi);
    cudaGetSymbolAddress((void**)&p_alo,  g_alo);
    cudaGetSymbolAddress((void**)&p_a2hi, g_a2hi);
    cudaGetSymbolAddress((void**)&p_a2lo, g_a2lo);
    cudaGetSymbolAddress((void**)&p_bh,   g_bh);

    cudaFuncSetAttribute((const void*)tgemm<0,true ,true >, cudaFuncAttributeMaxDynamicSharedMemorySize, SM_TOT);
    cudaFuncSetAttribute((const void*)tgemm<1,true ,false>, cudaFuncAttributeMaxDynamicSharedMemorySize, SM_TOT);
    cudaFuncSetAttribute((const void*)tgemm<2,true ,true >, cudaFuncAttributeMaxDynamicSharedMemorySize, SM_TOT);
    cudaFuncSetAttribute((const void*)tgemm<3,false,true >, cudaFuncAttributeMaxDynamicSharedMemorySize, SM_TOT);
    cudaFuncSetAttribute((const void*)tgemm<4,true ,false>, cudaFuncAttributeMaxDynamicSharedMemorySize, SM_TOT);

    const dim3 gBig(DIMN/256, M_TOK/128);     // (4, 128)
    const dim3 gDown(HIDC/256, M_TOK/128);    // (1, 128)

    // 1) norm + conv(+split)
    rmsnorm_kernel<<<M_TOK, 256>>>(x, norm_w, p_xn);
    dwconv_split_kernel<<<(M_TOK*DIMN)/256, 256>>>(p_xn, dw_w, dw_b, p_ahi, p_alo);
    // 2) y = xc @ pw^T + pw_b (+ xn for n>=ACT); emits y-split into a2
    whalf_kernel<<<(DIMN*DIMN)/1024, 256>>>(pw_w, p_bh);
    tgemm<0,true,true><<<gBig, 256, SM_TOT>>>(M_TOK, DIMN, DIMN, p_ahi, p_alo, p_bh,
        pw_b, p_y, p_a2hi, p_a2lo, p_xn, nullptr);
    // 3) recurrence adds into y[:, :ACT], patches split
    scan_p1<<<dim3(NCHUNK, BATCH), ACTC>>>(p_xn, alpha, beta, p_hend);
    scan_p2<<<dim3(NCHUNK, BATCH), ACTC>>>(p_xn, p_y, alpha, beta, p_hend, p_a2hi, p_a2lo);
    // 4) t1 = y @ W1^T + b1
    whalf_kernel<<<(DIMN*DIMN)/1024, 256>>>(W1_w, p_bh);
    tgemm<1,true,false><<<gBig, 256, SM_TOT>>>(M_TOK, DIMN, DIMN, p_a2hi, p_a2lo, p_bh,
        W1_b, p_t1, nullptr, nullptr, nullptr, nullptr);
    // 5) y2 = y + sigmoid(t1)*tanh(y @ W2^T + b2); emits y2-split into a
    whalf_kernel<<<(DIMN*DIMN)/1024, 256>>>(W2_w, p_bh);
    tgemm<2,true,true><<<gBig, 256, SM_TOT>>>(M_TOK, DIMN, DIMN, p_a2hi, p_a2lo, p_bh,
        W2_b, p_xc, p_ahi, p_alo, p_t1, p_y);
    // 6) h = gelu(y2 @ down^T + down_b); split only, into a2
    whalf_kernel<<<(HIDC*DIMN)/1024, 256>>>(down_w, p_bh);
    tgemm<3,false,true><<<gDown, 256, SM_TOT>>>(M_TOK, HIDC, DIMN, p_ahi, p_alo, p_bh,
        down_b, nullptr, p_a2hi, p_a2lo, nullptr, nullptr);
    // 7) out = y2 + h @ up^T + up_b + x
    whalf_kernel<<<(DIMN*HIDC)/1024, 256>>>(up_w, p_bh);
    tgemm<4,true,false><<<gBig, 256, SM_TOT>>>(M_TOK, DIMN, HIDC, p_a2hi, p_a2lo, p_bh,
        up_b, out, nullptr, nullptr, p_xc, x);
}

// round 12
// speedup vs baseline: 4.8395x; 1.1666x over previous
#include <cuda_runtime.h>
#include <cuda_fp16.h>
#include <math.h>
#include <stdint.h>

#define DIMN 1024
#define BATCH 8
#define LSEQ 2048
#define M_TOK (BATCH*LSEQ)
#define ACTC 256
#define HIDC 256
#define EPSV 1e-6f
#define NCHUNK 8
#define CHUNKL 256

// ---------------- scratch ---------------------------------------------------
__device__ float g_xn[(size_t)M_TOK*DIMN];
__device__ float g_xc[(size_t)M_TOK*DIMN];    // y2 fp32
__device__ float g_y [(size_t)M_TOK*DIMN];
__device__ float g_t1[(size_t)M_TOK*DIMN];
__device__ __half g_ahi [(size_t)M_TOK*DIMN];
__device__ __half g_alo [(size_t)M_TOK*DIMN];
__device__ __half g_a2hi[(size_t)M_TOK*DIMN];
__device__ __half g_a2lo[(size_t)M_TOK*DIMN];
__device__ __half g_bh  [(size_t)DIMN*DIMN];  // current weight, fp16 hi
__device__ float g_hend[BATCH*NCHUNK*ACTC];

// ---------------- helpers ---------------------------------------------------
__device__ __forceinline__ uint32_t smem_u32(const void* p) {
    uint32_t a;
    asm("{ .reg .u64 t; cvta.to.shared.u64 t, %1; cvt.u32.u64 %0, t; }" : "=r"(a) : "l"(p));
    return a;
}
__device__ __forceinline__ void cpasync16(uint32_t saddr, const void* g) {
    asm volatile("cp.async.cg.shared.global [%0], [%1], 16;" :: "r"(saddr), "l"(g) : "memory");
}
#define CP_COMMIT() asm volatile("cp.async.commit_group;" ::: "memory")

#define LDSM4(r, addr)                                                          \
    asm volatile("ldmatrix.sync.aligned.m8n8.x4.shared.b16 {%0,%1,%2,%3}, [%4];" \
        : "=r"((r)[0]), "=r"((r)[1]), "=r"((r)[2]), "=r"((r)[3]) : "r"(addr))

#define MMAH(c, a, b0, b1)                                                      \
    asm volatile("mma.sync.aligned.m16n8k16.row.col.f32.f16.f16.f32 "           \
        "{%0,%1,%2,%3},{%4,%5,%6,%7},{%8,%9},{%0,%1,%2,%3};"                    \
        : "+f"((c)[0]), "+f"((c)[1]), "+f"((c)[2]), "+f"((c)[3])                \
        : "r"((a)[0]), "r"((a)[1]), "r"((a)[2]), "r"((a)[3]), "r"(b0), "r"(b1))

// smem: rows of 32 fp16 padded to stride 40 halfs (80B) -> conflict-free LDSM
#define TPADH 40
#define AHI_B 0
#define ALO_B 10240
#define BH_B  20480
#define STAGE_B 40960
#define NSTAGE 4
#define SM_TOT (NSTAGE*STAGE_B)   /* 163840 */

// ---------------- split-fp16 2-pass HMMA GEMM: C = A[M,K]*B[N,K]^T ----------
// CTA 128x256, 512 threads (16 warps), warp tile 64x32.
// 4-stage cp.async pipeline, prefetch distance 2, single __syncthreads/iter.
// EPI 0: y   = acc + bias + (gn>=ACT ? aux1 : 0)
// EPI 1: t1  = acc + bias
// EPI 2: y2  = aux2 + sigmoid(aux1) * tanh(acc + bias)
// EPI 3: h   = gelu_exact(acc + bias)
// EPI 4: out = aux1 + acc + bias + aux2
template<int EPI, bool WF32, bool WSPLIT>
__global__ void __launch_bounds__(512, 1)
tgemm(int M, int N, int K,
      const __half* __restrict__ Ahi, const __half* __restrict__ Alo,
      const __half* __restrict__ Bh,
      const float* __restrict__ bias, float* __restrict__ C,
      __half* __restrict__ Chi, __half* __restrict__ Clo,
      const float* __restrict__ aux1, const float* __restrict__ aux2)
{
    extern __shared__ char sm[];
    const uint32_t sb = smem_u32(sm);
    const int t = threadIdx.x;
    const int bm = blockIdx.y * 128;
    const int bn = blockIdx.x * 256;

    const int wid = t >> 5, l = t & 31;
    const int wm = wid & 1;           // 2 x 64 rows
    const int wn = wid >> 1;          // 8 x 32 cols

    float c[4][4][4];
    #pragma unroll
    for (int i = 0; i < 4; i++)
        #pragma unroll
        for (int j = 0; j < 4; j++)
            #pragma unroll
            for (int k = 0; k < 4; k++) c[i][j][k] = 0.f;

    auto load_buf = [&](int buf, int k0) {
        uint32_t dbase = sb + (uint32_t)buf * STAGE_B;
        #pragma unroll
        for (int i = 0; i < 4; i++) {
            int cid = t + 512*i;                  // 0..2047
            if (cid < 1024) {                     // A hi/lo: 512 chunks each
                int row = (cid & 511) >> 2;
                int cc  = cid & 3;
                uint32_t doff = (uint32_t)(row*80 + cc*16);
                const __half* src = (cid < 512) ? Ahi : Alo;
                uint32_t db = (cid < 512) ? AHI_B : ALO_B;
                cpasync16(dbase + db + doff, src + (size_t)(bm+row)*K + k0 + cc*8);
            } else {                              // B hi: 1024 chunks
                int q = cid - 1024;
                int row = q >> 2;
                int cc  = q & 3;
                cpasync16(dbase + BH_B + (uint32_t)(row*80 + cc*16),
                          Bh + (size_t)(bn+row)*K + k0 + cc*8);
            }
        }
        CP_COMMIT();
    };

    const int KB = K >> 5;
    load_buf(0, 0);
    if (KB > 1) load_buf(1, 32); else CP_COMMIT();

    const uint32_t acol = (uint32_t)((l >> 4) << 3);
    const int arow0 = wm*64 + (l & 15);
    const int brow0 = wn*32 + (l & 7) + ((l & 16) >> 1);
    const uint32_t bcol = (uint32_t)(l & 8);

    for (int kb = 0; kb < KB; kb++) {
        if (kb + 2 < KB) load_buf((kb+2) % NSTAGE, (kb+2)*32); else CP_COMMIT();
        asm volatile("cp.async.wait_group 2;" ::: "memory");
        __syncthreads();

        uint32_t base = sb + (uint32_t)(kb % NSTAGE) * STAGE_B;
        #pragma unroll
        for (int ks = 0; ks < 2; ks++) {
            uint32_t ahi[4][4], alo[4][4];
            #pragma unroll
            for (int mt = 0; mt < 4; mt++) {
                uint32_t off = (uint32_t)((arow0 + mt*16)*TPADH + acol + ks*16) * 2;
                LDSM4(ahi[mt], base + AHI_B + off);
                LDSM4(alo[mt], base + ALO_B + off);
            }
            #pragma unroll
            for (int j = 0; j < 2; j++) {
                uint32_t b[4];
                uint32_t off = (uint32_t)((brow0 + j*16)*TPADH + bcol + ks*16) * 2;
                LDSM4(b, base + BH_B + off);
                #pragma unroll
                for (int mt = 0; mt < 4; mt++) {
                    MMAH(c[mt][j*2+0], ahi[mt], b[0], b[1]);
                    MMAH(c[mt][j*2+0], alo[mt], b[0], b[1]);
                    MMAH(c[mt][j*2+1], ahi[mt], b[2], b[3]);
                    MMAH(c[mt][j*2+1], alo[mt], b[2], b[3]);
                }
            }
        }
    }

    __syncthreads();

    // ---- epilogue ----
    const int gid = l >> 2, tig = l & 3;
    #pragma unroll
    for (int mt = 0; mt < 4; mt++) {
        #pragma unroll
        for (int half = 0; half < 2; half++) {
            int gm = bm + wm*64 + mt*16 + gid + half*8;
            size_t rowoff = (size_t)gm * N;
            #pragma unroll
            for (int nt = 0; nt < 4; nt++) {
                int gn = bn + wn*32 + nt*8 + tig*2;
                float v0 = c[mt][nt][half*2+0] + bias[gn];
                float v1 = c[mt][nt][half*2+1] + bias[gn+1];
                float2 o;
                if (EPI == 0) {
                    if (gn >= ACTC) {
                        float2 a = *(const float2*)(aux1 + rowoff + gn);
                        v0 += a.x; v1 += a.y;
                    }
                    o.x = v0; o.y = v1;
                } else if (EPI == 1) {
                    o.x = v0; o.y = v1;
                } else if (EPI == 2) {
                    float2 a = *(const float2*)(aux1 + rowoff + gn);
                    float2 b = *(const float2*)(aux2 + rowoff + gn);
                    o.x = b.x + tanhf(v0) / (1.f + expf(-a.x));
                    o.y = b.y + tanhf(v1) / (1.f + expf(-a.y));
                } else if (EPI == 3) {
                    o.x = 0.5f*v0*(1.f + erff(v0*0.70710678118654752f));
                    o.y = 0.5f*v1*(1.f + erff(v1*0.70710678118654752f));
                } else {
                    float2 a = *(const float2*)(aux1 + rowoff + gn);
                    float2 b = *(const float2*)(aux2 + rowoff + gn);
                    o.x = a.x + v0 + b.x;
                    o.y = a.y + v1 + b.y;
                }
                if (WF32) *(float2*)(C + rowoff + gn) = o;
                if (WSPLIT) {
                    __half h0 = __float2half(o.x), h1 = __float2half(o.y);
                    __half l0 = __float2half(o.x - __half2float(h0));
                    __half l1 = __float2half(o.y - __half2float(h1));
                    *(__half2*)(Chi + rowoff + gn) = __half2(h0, h1);
                    *(__half2*)(Clo + rowoff + gn) = __half2(l0, l1);
                }
            }
        }
    }
}

// ---------------- fp32 -> fp16 (weights, hi only) ---------------------------
__global__ void whalf_kernel(const float* __restrict__ s, __half* __restrict__ h)
{
    int i = blockIdx.x * 256 + threadIdx.x;
    float4 v = ((const float4*)s)[i];
    ((__half2*)h)[2*i]   = __half2(__float2half(v.x), __float2half(v.y));
    ((__half2*)h)[2*i+1] = __half2(__float2half(v.z), __float2half(v.w));
}

// ---------------- RMSNorm ---------------------------------------------------
__global__ void rmsnorm_kernel(const float* __restrict__ x,
                               const float* __restrict__ w,
                               float* __restrict__ xn)
{
    int m = blockIdx.x;
    int t = threadIdx.x;
    const float4* xr = (const float4*)(x + (size_t)m*DIMN);
    float4*       xo = (float4*)(xn + (size_t)m*DIMN);
    float4 v = xr[t];
    float ss = v.x*v.x + v.y*v.y + v.z*v.z + v.w*v.w;
    __shared__ float red[8];
    #pragma unroll
    for (int o = 16; o > 0; o >>= 1) ss += __shfl_xor_sync(0xffffffffu, ss, o);
    if ((t & 31) == 0) red[t >> 5] = ss;
    __syncthreads();
    if (t < 8) {
        float s = red[t];
        #pragma unroll
        for (int o = 4; o > 0; o >>= 1) s += __shfl_xor_sync(0xffu, s, o);
        if (t == 0) red[0] = s;
    }
    __syncthreads();
    float scale = rsqrtf(red[0] * (1.0f/DIMN) + EPSV);
    float4 wv = ((const float4*)w)[t];
    float4 o4;
    o4.x = v.x*scale*wv.x;  o4.y = v.y*scale*wv.y;
    o4.z = v.z*scale*wv.z;  o4.w = v.w*scale*wv.w;
    xo[t] = o4;
}

// ---------------- depthwise conv + fused fp16 split -------------------------
__global__ void dwconv_split_kernel(const float* __restrict__ xn,
                                    const float* __restrict__ dw_w,
                                    const float* __restrict__ dw_b,
                                    __half* __restrict__ hi,
                                    __half* __restrict__ lo)
{
    int idx = blockIdx.x * 256 + threadIdx.x;
    int d = idx & (DIMN - 1);
    int m = idx >> 10;
    int l = m & (LSEQ - 1);
    float w0 = dw_w[d*5+0], w1 = dw_w[d*5+1], w2 = dw_w[d*5+2],
          w3 = dw_w[d*5+3], w4 = dw_w[d*5+4];
    float acc = dw_b[d];
    if (l >= 2)        acc += xn[idx - 2*DIMN] * w0;
    if (l >= 1)        acc += xn[idx - 1*DIMN] * w1;
    acc += xn[idx] * w2;
    if (l <= LSEQ - 2) acc += xn[idx + 1*DIMN] * w3;
    if (l <= LSEQ - 3) acc += xn[idx + 2*DIMN] * w4;
    __half h = __float2half(acc);
    hi[idx] = h;
    lo[idx] = __float2half(acc - __half2float(h));
}

// ---------------- chunked scan ----------------------------------------------
__global__ void scan_p1(const float* __restrict__ xn,
                        const float* __restrict__ alpha,
                        const float* __restrict__ beta,
                        float* __restrict__ hend)
{
    int c = threadIdx.x, ch = blockIdx.x, b = blockIdx.y;
    float a = alpha[c], be = beta[c], h = 0.f;
    size_t base = ((size_t)b*LSEQ + ch*CHUNKL)*DIMN + c;
    for (int i = 0; i < CHUNKL; i++) { h = fmaf(a, h, be*xn[base]); base += DIMN; }
    hend[(b*NCHUNK + ch)*ACTC + c] = h;
}

__global__ void scan_p2(const float* __restrict__ xn,
                        float* __restrict__ y,
                        const float* __restrict__ alpha,
                        const float* __restrict__ beta,
                        const float* __restrict__ hend,
                        __half* __restrict__ yhi,
                        __half* __restrict__ ylo)
{
    int c = threadIdx.x, ch = blockIdx.x, b = blockIdx.y;
    float a = alpha[c], be = beta[c];
    float ap = a;
    #pragma unroll
    for (int i = 0; i < 8; i++) ap = ap*ap;       // a^256
    float h = 0.f;
    for (int j = 0; j < ch; j++) h = ap*h + hend[(b*NCHUNK + j)*ACTC + c];
    size_t base = ((size_t)b*LSEQ + ch*CHUNKL)*DIMN + c;
    for (int i = 0; i < CHUNKL; i++) {
        h = fmaf(a, h, be*xn[base]);
        float yn = y[base] + h;
        y[base] = yn;
        __half hv = __float2half(yn);
        yhi[base] = hv;
        ylo[base] = __float2half(yn - __half2float(hv));
        base += DIMN;
    }
}

// ---------------- host launcher ---------------------------------------------
extern "C" void kernel_launch(void* const* d_in, const int* in_sizes, int n_in,
                              void* d_out, int out_size)
{
    const float* x      = (const float*)d_in[0];
    const float* norm_w = (const float*)d_in[1];
    const float* dw_w   = (const float*)d_in[2];
    const float* dw_b   = (const float*)d_in[3];
    const float* pw_w   = (const float*)d_in[4];
    const float* pw_b   = (const float*)d_in[5];
    const float* alpha  = (const float*)d_in[6];
    const float* beta   = (const float*)d_in[7];
    const float* W1_w   = (const float*)d_in[8];
    const float* W1_b   = (const float*)d_in[9];
    const float* W2_w   = (const float*)d_in[10];
    const float* W2_b   = (const float*)d_in[11];
    const float* down_w = (const float*)d_in[12];
    const float* down_b = (const float*)d_in[13];
    const float* up_w   = (const float*)d_in[14];
    const float* up_b   = (const float*)d_in[15];
    float* out = (float*)d_out;

    float *p_xn, *p_xc, *p_y, *p_t1, *p_hend;
    __half *p_ahi, *p_alo, *p_a2hi, *p_a2lo, *p_bh;
    cudaGetSymbolAddress((void**)&p_xn, g_xn);
    cudaGetSymbolAddress((void**)&p_xc, g_xc);
    cudaGetSymbolAddress((void**)&p_y,  g_y);
    cudaGetSymbolAddress((void**)&p_t1, g_t1);
    cudaGetSymbolAddress((void**)&p_hend, g_hend);
    cudaGetSymbolAddress((void**)&p_ahi,  g_ahi);
    cudaGetSymbolAddress((void**)&p_alo,  g_alo);
    cudaGetSymbolAddress((void**)&p_a2hi, g_a2hi);
    cudaGetSymbolAddress((void**)&p_a2lo, g_a2lo);
    cudaGetSymbolAddress((void**)&p_bh,   g_bh);

    cudaFuncSetAttribute((const void*)tgemm<0,true ,true >, cudaFuncAttributeMaxDynamicSharedMemorySize, SM_TOT);
    cudaFuncSetAttribute((const void*)tgemm<1,true ,false>, cudaFuncAttributeMaxDynamicSharedMemorySize, SM_TOT);
    cudaFuncSetAttribute((const void*)tgemm<2,true ,true >, cudaFuncAttributeMaxDynamicSharedMemorySize, SM_TOT);
    cudaFuncSetAttribute((const void*)tgemm<3,false,true >, cudaFuncAttributeMaxDynamicSharedMemorySize, SM_TOT);
    cudaFuncSetAttribute((const void*)tgemm<4,true ,false>, cudaFuncAttributeMaxDynamicSharedMemorySize, SM_TOT);

    const dim3 gBig(DIMN/256, M_TOK/128);     // (4, 128)
    const dim3 gDown(HIDC/256, M_TOK/128);    // (1, 128)

    // 1) norm + conv(+split)
    rmsnorm_kernel<<<M_TOK, 256>>>(x, norm_w, p_xn);
    dwconv_split_kernel<<<(M_TOK*DIMN)/256, 256>>>(p_xn, dw_w, dw_b, p_ahi, p_alo);
    // 2) y = xc @ pw^T + pw_b (+ xn for n>=ACT); emits y-split into a2
    whalf_kernel<<<(DIMN*DIMN)/1024, 256>>>(pw_w, p_bh);
    tgemm<0,true,true><<<gBig, 512, SM_TOT>>>(M_TOK, DIMN, DIMN, p_ahi, p_alo, p_bh,
        pw_b, p_y, p_a2hi, p_a2lo, p_xn, nullptr);
    // 3) recurrence adds into y[:, :ACT], patches split
    scan_p1<<<dim3(NCHUNK, BATCH), ACTC>>>(p_xn, alpha, beta, p_hend);
    scan_p2<<<dim3(NCHUNK, BATCH), ACTC>>>(p_xn, p_y, alpha, beta, p_hend, p_a2hi, p_a2lo);
    // 4) t1 = y @ W1^T + b1
    whalf_kernel<<<(DIMN*DIMN)/1024, 256>>>(W1_w, p_bh);
    tgemm<1,true,false><<<gBig, 512, SM_TOT>>>(M_TOK, DIMN, DIMN, p_a2hi, p_a2lo, p_bh,
        W1_b, p_t1, nullptr, nullptr, nullptr, nullptr);
    // 5) y2 = y + sigmoid(t1)*tanh(y @ W2^T + b2); emits y2-split into a
    whalf_kernel<<<(DIMN*DIMN)/1024, 256>>>(W2_w, p_bh);
    tgemm<2,true,true><<<gBig, 512, SM_TOT>>>(M_TOK, DIMN, DIMN, p_a2hi, p_a2lo, p_bh,
        W2_b, p_xc, p_ahi, p_alo, p_t1, p_y);
    // 6) h = gelu(y2 @ down^T + down_b); split only, into a2
    whalf_kernel<<<(HIDC*DIMN)/1024, 256>>>(down_w, p_bh);
    tgemm<3,false,true><<<gDown, 512, SM_TOT>>>(M_TOK, HIDC, DIMN, p_ahi, p_alo, p_bh,
        down_b, nullptr, p_a2hi, p_a2lo, nullptr, nullptr);
    // 7) out = y2 + h @ up^T + up_b + x
    whalf_kernel<<<(DIMN*HIDC)/1024, 256>>>(up_w, p_bh);
    tgemm<4,true,false><<<gBig, 512, SM_TOT>>>(M_TOK, DIMN, HIDC, p_a2hi, p_a2lo, p_bh,
        up_b, out, nullptr, nullptr, p_xc, x);
}

// round 16
// speedup vs baseline: 6.4986x; 1.3428x over previous
#include <cuda_runtime.h>
#include <cuda_fp16.h>
#include <math.h>
#include <stdint.h>

#define DIMN 1024
#define BATCH 8
#define LSEQ 2048
#define M_TOK (BATCH*LSEQ)
#define ACTC 256
#define HIDC 256
#define EPSV 1e-6f
#define NCHUNK 8
#define CHUNKL 256

// ---------------- scratch ---------------------------------------------------
__device__ float g_xn[(size_t)M_TOK*DIMN];
__device__ float g_xc[(size_t)M_TOK*DIMN];    // y2 fp32
__device__ float g_y [(size_t)M_TOK*DIMN];
__device__ float g_t1[(size_t)M_TOK*DIMN];
__device__ __half g_ahi [(size_t)M_TOK*DIMN];
__device__ __half g_a2hi[(size_t)M_TOK*DIMN];
__device__ __half g_bh  [(size_t)DIMN*DIMN];  // current weight, fp16
__device__ float g_hend[BATCH*NCHUNK*ACTC];

// ---------------- helpers ---------------------------------------------------
__device__ __forceinline__ uint32_t smem_u32(const void* p) {
    uint32_t a;
    asm("{ .reg .u64 t; cvta.to.shared.u64 t, %1; cvt.u32.u64 %0, t; }" : "=r"(a) : "l"(p));
    return a;
}
__device__ __forceinline__ void cpasync16(uint32_t saddr, const void* g) {
    asm volatile("cp.async.cg.shared.global [%0], [%1], 16;" :: "r"(saddr), "l"(g) : "memory");
}
#define CP_COMMIT() asm volatile("cp.async.commit_group;" ::: "memory")

#define LDSM4(r, addr)                                                          \
    asm volatile("ldmatrix.sync.aligned.m8n8.x4.shared.b16 {%0,%1,%2,%3}, [%4];" \
        : "=r"((r)[0]), "=r"((r)[1]), "=r"((r)[2]), "=r"((r)[3]) : "r"(addr))

#define MMAH(c, a, b0, b1)                                                      \
    asm volatile("mma.sync.aligned.m16n8k16.row.col.f32.f16.f16.f32 "           \
        "{%0,%1,%2,%3},{%4,%5,%6,%7},{%8,%9},{%0,%1,%2,%3};"                    \
        : "+f"((c)[0]), "+f"((c)[1]), "+f"((c)[2]), "+f"((c)[3])                \
        : "r"((a)[0]), "r"((a)[1]), "r"((a)[2]), "r"((a)[3]), "r"(b0), "r"(b1))

// smem: rows of 32 fp16 padded to stride 40 halfs (80B) -> conflict-free LDSM
#define TPADH 40
#define AHI_B 0
#define BH_B  10240
#define STAGE_B 30720
#define NSTAGE 4
#define SM_TOT (NSTAGE*STAGE_B)   /* 122880 */

// ---------------- fp16 single-pass HMMA GEMM: C = A[M,K]*B[N,K]^T -----------
// CTA 128x256, 512 threads (16 warps), warp tile 64x32.
// 4-stage cp.async pipeline, prefetch distance 2, single __syncthreads/iter.
// All MMAs per j-group hit distinct accumulators (no RAW chains).
// EPI 0: y   = acc + bias + (gn>=ACT ? aux1 : 0)
// EPI 1: t1  = acc + bias
// EPI 2: y2  = aux2 + sigmoid(aux1) * tanh(acc + bias)
// EPI 3: h   = gelu_exact(acc + bias)
// EPI 4: out = aux1 + acc + bias + aux2
template<int EPI, bool WF32, bool WSPLIT>
__global__ void __launch_bounds__(512, 1)
tgemm(int M, int N, int K,
      const __half* __restrict__ Ah, const __half* __restrict__ Bh,
      const float* __restrict__ bias, float* __restrict__ C,
      __half* __restrict__ Chi,
      const float* __restrict__ aux1, const float* __restrict__ aux2)
{
    extern __shared__ char sm[];
    const uint32_t sb = smem_u32(sm);
    const int t = threadIdx.x;
    const int bm = blockIdx.y * 128;
    const int bn = blockIdx.x * 256;

    const int wid = t >> 5, l = t & 31;
    const int wm = wid & 1;           // 2 x 64 rows
    const int wn = wid >> 1;          // 8 x 32 cols

    float c[4][4][4];
    #pragma unroll
    for (int i = 0; i < 4; i++)
        #pragma unroll
        for (int j = 0; j < 4; j++)
            #pragma unroll
            for (int k = 0; k < 4; k++) c[i][j][k] = 0.f;

    auto load_buf = [&](int buf, int k0) {
        uint32_t dbase = sb + (uint32_t)buf * STAGE_B;
        #pragma unroll
        for (int i = 0; i < 3; i++) {
            int cid = t + 512*i;                  // 0..1535
            if (cid < 512) {                      // A: 128 rows x 4 chunks
                int row = cid >> 2, cc = cid & 3;
                cpasync16(dbase + AHI_B + (uint32_t)(row*80 + cc*16),
                          Ah + (size_t)(bm+row)*K + k0 + cc*8);
            } else {                              // B: 256 rows x 4 chunks
                int q = cid - 512;
                int row = q >> 2, cc = q & 3;
                cpasync16(dbase + BH_B + (uint32_t)(row*80 + cc*16),
                          Bh + (size_t)(bn+row)*K + k0 + cc*8);
            }
        }
        CP_COMMIT();
    };

    const int KB = K >> 5;
    load_buf(0, 0);
    if (KB > 1) load_buf(1, 32); else CP_COMMIT();

    const uint32_t acol = (uint32_t)((l >> 4) << 3);
    const int arow0 = wm*64 + (l & 15);
    const int brow0 = wn*32 + (l & 7) + ((l & 16) >> 1);
    const uint32_t bcol = (uint32_t)(l & 8);

    for (int kb = 0; kb < KB; kb++) {
        if (kb + 2 < KB) load_buf((kb+2) % NSTAGE, (kb+2)*32); else CP_COMMIT();
        asm volatile("cp.async.wait_group 2;" ::: "memory");
        __syncthreads();

        uint32_t base = sb + (uint32_t)(kb % NSTAGE) * STAGE_B;
        #pragma unroll
        for (int ks = 0; ks < 2; ks++) {
            uint32_t a[4][4];
            #pragma unroll
            for (int mt = 0; mt < 4; mt++) {
                uint32_t off = (uint32_t)((arow0 + mt*16)*TPADH + acol + ks*16) * 2;
                LDSM4(a[mt], base + AHI_B + off);
            }
            #pragma unroll
            for (int j = 0; j < 2; j++) {
                uint32_t b[4];
                uint32_t off = (uint32_t)((brow0 + j*16)*TPADH + bcol + ks*16) * 2;
                LDSM4(b, base + BH_B + off);
                #pragma unroll
                for (int mt = 0; mt < 4; mt++)
                    MMAH(c[mt][j*2+0], a[mt], b[0], b[1]);
                #pragma unroll
                for (int mt = 0; mt < 4; mt++)
                    MMAH(c[mt][j*2+1], a[mt], b[2], b[3]);
            }
        }
    }

    __syncthreads();

    // ---- epilogue ----
    const int gid = l >> 2, tig = l & 3;
    #pragma unroll
    for (int mt = 0; mt < 4; mt++) {
        #pragma unroll
        for (int half = 0; half < 2; half++) {
            int gm = bm + wm*64 + mt*16 + gid + half*8;
            size_t rowoff = (size_t)gm * N;
            #pragma unroll
            for (int nt = 0; nt < 4; nt++) {
                int gn = bn + wn*32 + nt*8 + tig*2;
                float v0 = c[mt][nt][half*2+0] + bias[gn];
                float v1 = c[mt][nt][half*2+1] + bias[gn+1];
                float2 o;
                if (EPI == 0) {
                    if (gn >= ACTC) {
                        float2 a = *(const float2*)(aux1 + rowoff + gn);
                        v0 += a.x; v1 += a.y;
                    }
                    o.x = v0; o.y = v1;
                } else if (EPI == 1) {
                    o.x = v0; o.y = v1;
                } else if (EPI == 2) {
                    float2 a = *(const float2*)(aux1 + rowoff + gn);
                    float2 b = *(const float2*)(aux2 + rowoff + gn);
                    o.x = b.x + tanhf(v0) / (1.f + expf(-a.x));
                    o.y = b.y + tanhf(v1) / (1.f + expf(-a.y));
                } else if (EPI == 3) {
                    o.x = 0.5f*v0*(1.f + erff(v0*0.70710678118654752f));
                    o.y = 0.5f*v1*(1.f + erff(v1*0.70710678118654752f));
                } else {
                    float2 a = *(const float2*)(aux1 + rowoff + gn);
                    float2 b = *(const float2*)(aux2 + rowoff + gn);
                    o.x = a.x + v0 + b.x;
                    o.y = a.y + v1 + b.y;
                }
                if (WF32) *(float2*)(C + rowoff + gn) = o;
                if (WSPLIT) {
                    *(__half2*)(Chi + rowoff + gn) =
                        __half2(__float2half(o.x), __float2half(o.y));
                }
            }
        }
    }
}

// ---------------- fp32 -> fp16 (weights) ------------------------------------
__global__ void whalf_kernel(const float* __restrict__ s, __half* __restrict__ h)
{
    int i = blockIdx.x * 256 + threadIdx.x;
    float4 v = ((const float4*)s)[i];
    ((__half2*)h)[2*i]   = __half2(__float2half(v.x), __float2half(v.y));
    ((__half2*)h)[2*i+1] = __half2(__float2half(v.z), __float2half(v.w));
}

// ---------------- RMSNorm ---------------------------------------------------
__global__ void rmsnorm_kernel(const float* __restrict__ x,
                               const float* __restrict__ w,
                               float* __restrict__ xn)
{
    int m = blockIdx.x;
    int t = threadIdx.x;
    const float4* xr = (const float4*)(x + (size_t)m*DIMN);
    float4*       xo = (float4*)(xn + (size_t)m*DIMN);
    float4 v = xr[t];
    float ss = v.x*v.x + v.y*v.y + v.z*v.z + v.w*v.w;
    __shared__ float red[8];
    #pragma unroll
    for (int o = 16; o > 0; o >>= 1) ss += __shfl_xor_sync(0xffffffffu, ss, o);
    if ((t & 31) == 0) red[t >> 5] = ss;
    __syncthreads();
    if (t < 8) {
        float s = red[t];
        #pragma unroll
        for (int o = 4; o > 0; o >>= 1) s += __shfl_xor_sync(0xffu, s, o);
        if (t == 0) red[0] = s;
    }
    __syncthreads();
    float scale = rsqrtf(red[0] * (1.0f/DIMN) + EPSV);
    float4 wv = ((const float4*)w)[t];
    float4 o4;
    o4.x = v.x*scale*wv.x;  o4.y = v.y*scale*wv.y;
    o4.z = v.z*scale*wv.z;  o4.w = v.w*scale*wv.w;
    xo[t] = o4;
}

// ---------------- depthwise conv + fp16 out ---------------------------------
__global__ void dwconv_split_kernel(const float* __restrict__ xn,
                                    const float* __restrict__ dw_w,
                                    const float* __restrict__ dw_b,
                                    __half* __restrict__ hi)
{
    int idx = blockIdx.x * 256 + threadIdx.x;
    int d = idx & (DIMN - 1);
    int m = idx >> 10;
    int l = m & (LSEQ - 1);
    float w0 = dw_w[d*5+0], w1 = dw_w[d*5+1], w2 = dw_w[d*5+2],
          w3 = dw_w[d*5+3], w4 = dw_w[d*5+4];
    float acc = dw_b[d];
    if (l >= 2)        acc += xn[idx - 2*DIMN] * w0;
    if (l >= 1)        acc += xn[idx - 1*DIMN] * w1;
    acc += xn[idx] * w2;
    if (l <= LSEQ - 2) acc += xn[idx + 1*DIMN] * w3;
    if (l <= LSEQ - 3) acc += xn[idx + 2*DIMN] * w4;
    hi[idx] = __float2half(acc);
}

// ---------------- chunked scan ----------------------------------------------
__global__ void scan_p1(const float* __restrict__ xn,
                        const float* __restrict__ alpha,
                        const float* __restrict__ beta,
                        float* __restrict__ hend)
{
    int c = threadIdx.x, ch = blockIdx.x, b = blockIdx.y;
    float a = alpha[c], be = beta[c], h = 0.f;
    size_t base = ((size_t)b*LSEQ + ch*CHUNKL)*DIMN + c;
    for (int i = 0; i < CHUNKL; i++) { h = fmaf(a, h, be*xn[base]); base += DIMN; }
    hend[(b*NCHUNK + ch)*ACTC + c] = h;
}

__global__ void scan_p2(const float* __restrict__ xn,
                        float* __restrict__ y,
                        const float* __restrict__ alpha,
                        const float* __restrict__ beta,
                        const float* __restrict__ hend,
                        __half* __restrict__ yhi)
{
    int c = threadIdx.x, ch = blockIdx.x, b = blockIdx.y;
    float a = alpha[c], be = beta[c];
    float ap = a;
    #pragma unroll
    for (int i = 0; i < 8; i++) ap = ap*ap;       // a^256
    float h = 0.f;
    for (int j = 0; j < ch; j++) h = ap*h + hend[(b*NCHUNK + j)*ACTC + c];
    size_t base = ((size_t)b*LSEQ + ch*CHUNKL)*DIMN + c;
    for (int i = 0; i < CHUNKL; i++) {
        h = fmaf(a, h, be*xn[base]);
        float yn = y[base] + h;
        y[base] = yn;
        yhi[base] = __float2half(yn);
        base += DIMN;
    }
}

// ---------------- host launcher ---------------------------------------------
extern "C" void kernel_launch(void* const* d_in, const int* in_sizes, int n_in,
                              void* d_out, int out_size)
{
    const float* x      = (const float*)d_in[0];
    const float* norm_w = (const float*)d_in[1];
    const float* dw_w   = (const float*)d_in[2];
    const float* dw_b   = (const float*)d_in[3];
    const float* pw_w   = (const float*)d_in[4];
    const float* pw_b   = (const float*)d_in[5];
    const float* alpha  = (const float*)d_in[6];
    const float* beta   = (const float*)d_in[7];
    const float* W1_w   = (const float*)d_in[8];
    const float* W1_b   = (const float*)d_in[9];
    const float* W2_w   = (const float*)d_in[10];
    const float* W2_b   = (const float*)d_in[11];
    const float* down_w = (const float*)d_in[12];
    const float* down_b = (const float*)d_in[13];
    const float* up_w   = (const float*)d_in[14];
    const float* up_b   = (const float*)d_in[15];
    float* out = (float*)d_out;

    float *p_xn, *p_xc, *p_y, *p_t1, *p_hend;
    __half *p_ahi, *p_a2hi, *p_bh;
    cudaGetSymbolAddress((void**)&p_xn, g_xn);
    cudaGetSymbolAddress((void**)&p_xc, g_xc);
    cudaGetSymbolAddress((void**)&p_y,  g_y);
    cudaGetSymbolAddress((void**)&p_t1, g_t1);
    cudaGetSymbolAddress((void**)&p_hend, g_hend);
    cudaGetSymbolAddress((void**)&p_ahi,  g_ahi);
    cudaGetSymbolAddress((void**)&p_a2hi, g_a2hi);
    cudaGetSymbolAddress((void**)&p_bh,   g_bh);

    cudaFuncSetAttribute((const void*)tgemm<0,true ,true >, cudaFuncAttributeMaxDynamicSharedMemorySize, SM_TOT);
    cudaFuncSetAttribute((const void*)tgemm<1,true ,false>, cudaFuncAttributeMaxDynamicSharedMemorySize, SM_TOT);
    cudaFuncSetAttribute((const void*)tgemm<2,true ,true >, cudaFuncAttributeMaxDynamicSharedMemorySize, SM_TOT);
    cudaFuncSetAttribute((const void*)tgemm<3,false,true >, cudaFuncAttributeMaxDynamicSharedMemorySize, SM_TOT);
    cudaFuncSetAttribute((const void*)tgemm<4,true ,false>, cudaFuncAttributeMaxDynamicSharedMemorySize, SM_TOT);

    const dim3 gBig(DIMN/256, M_TOK/128);     // (4, 128)
    const dim3 gDown(HIDC/256, M_TOK/128);    // (1, 128)

    // 1) norm + conv(+fp16)
    rmsnorm_kernel<<<M_TOK, 256>>>(x, norm_w, p_xn);
    dwconv_split_kernel<<<(M_TOK*DIMN)/256, 256>>>(p_xn, dw_w, dw_b, p_ahi);
    // 2) y = xc @ pw^T + pw_b (+ xn for n>=ACT); emits y fp16 into a2
    whalf_kernel<<<(DIMN*DIMN)/1024, 256>>>(pw_w, p_bh);
    tgemm<0,true,true><<<gBig, 512, SM_TOT>>>(M_TOK, DIMN, DIMN, p_ahi, p_bh,
        pw_b, p_y, p_a2hi, p_xn, nullptr);
    // 3) recurrence adds into y[:, :ACT], patches fp16 copy
    scan_p1<<<dim3(NCHUNK, BATCH), ACTC>>>(p_xn, alpha, beta, p_hend);
    scan_p2<<<dim3(NCHUNK, BATCH), ACTC>>>(p_xn, p_y, alpha, beta, p_hend, p_a2hi);
    // 4) t1 = y @ W1^T + b1
    whalf_kernel<<<(DIMN*DIMN)/1024, 256>>>(W1_w, p_bh);
    tgemm<1,true,false><<<gBig, 512, SM_TOT>>>(M_TOK, DIMN, DIMN, p_a2hi, p_bh,
        W1_b, p_t1, nullptr, nullptr, nullptr);
    // 5) y2 = y + sigmoid(t1)*tanh(y @ W2^T + b2); emits y2 fp16 into a
    whalf_kernel<<<(DIMN*DIMN)/1024, 256>>>(W2_w, p_bh);
    tgemm<2,true,true><<<gBig, 512, SM_TOT>>>(M_TOK, DIMN, DIMN, p_a2hi, p_bh,
        W2_b, p_xc, p_ahi, p_t1, p_y);
    // 6) h = gelu(y2 @ down^T + down_b); fp16 only, into a2
    whalf_kernel<<<(HIDC*DIMN)/1024, 256>>>(down_w, p_bh);
    tgemm<3,false,true><<<gDown, 512, SM_TOT>>>(M_TOK, HIDC, DIMN, p_ahi, p_bh,
        down_b, nullptr, p_a2hi, nullptr, nullptr);
    // 7) out = y2 + h @ up^T + up_b + x
    whalf_kernel<<<(DIMN*HIDC)/1024, 256>>>(up_w, p_bh);
    tgemm<4,true,false><<<gBig, 512, SM_TOT>>>(M_TOK, DIMN, HIDC, p_a2hi, p_bh,
        up_b, out, nullptr, p_xc, x);
}